// round 14
// baseline (speedup 1.0000x reference)
#include <cuda_runtime.h>
#include <math.h>

// Problem constants
#define N        10000
#define DF       32
#define ITERS    4
#define JSPLIT   28             // j-range splits
#define PCHUNK   183            // packed j-pairs per split (366 j)
#define NPAIR_PAD (JSPLIT * PCHUNK)    // 5124 pairs = 10248 j slots
#define NSLOTS_J (2 * NPAIR_PAD)       // 10248
#define ITILE    256            // threads per block
#define IPT      2              // i-points per thread
#define IBLK     (ITILE * IPT)  // 512 i per block
#define NITILE   20             // i-slots 10240; grid 20*28 = 560, 1 wave @ occ 4
#define NSLOTS_I 10240
#define ZSCALE   16384.0f
#define SENTC    1.0e6f

// Scratch (static device arrays; cudaMalloc is forbidden)
__device__ float g_pairsA[NPAIR_PAD * 12];
__device__ float g_pairsB[NPAIR_PAD * 12];
__device__ int   g_cnt[ITERS * NITILE];        // stripe completion counters
__device__ float g_part[JSPLIT * NSLOTS_I * 12];
__device__ float g_h[ITERS * N * DF];
__device__ float g_stats[ITERS * DF * 2];
__device__ float g_w[ITERS * N * 3];

// ---------------------------------------------------------------------------
// Pair record (12 words per packed j-pair):
//   [0..7]  x0 x1 y0 y1 z0 z1 nu0 nu1   (nu = -0.5|x|^2; also the addends)
//   [8,9]   round(z*2^14) s32 (zf0, zf1)
//   [10,11] pad
// ---------------------------------------------------------------------------
__device__ __forceinline__ void write_rec(float* buf, int s, float x, float y, float z) {
    int p = s >> 1, h = s & 1;
    float nu = -0.5f * (x * x + y * y + z * z);
    float* rec = buf + p * 12;
    rec[0 + h] = x;
    rec[2 + h] = y;
    rec[4 + h] = z;
    rec[6 + h] = nu;
    ((int*)rec)[8 + h] = __float2int_rn(z * ZSCALE);
}

// Per-pair accumulate for one i-point (R13-proven body).
#define PAIR_ACC(SX1,SY1,SX2,SY2,SX3,SY3,AZ1,AZ2,AZ3,AC1,AC2,FC3,XI2,YI2,ZI2,TH1,TH2,TH3) \
    asm("{\n\t" \
        ".reg .b64  t64;\n\t" \
        ".reg .f32  vl, vh, x0, x1, y0, y1;\n\t" \
        ".reg .pred pl1, pl2, pl3, ph1, ph2, ph3;\n\t" \
        "fma.rn.f32x2 t64, %12, %15, %18;\n\t" \
        "fma.rn.f32x2 t64, %13, %16, t64;\n\t" \
        "fma.rn.f32x2 t64, %14, %17, t64;\n\t" \
        "mov.b64 {vl, vh}, t64;\n\t" \
        "mov.b64 {x0, x1}, %15;\n\t" \
        "mov.b64 {y0, y1}, %16;\n\t" \
        "setp.ge.f32 pl1, vl, %19;\n\t" \
        "setp.ge.f32 pl2, vl, %20;\n\t" \
        "setp.ge.f32 pl3, vl, %21;\n\t" \
        "setp.ge.f32 ph1, vh, %19;\n\t" \
        "setp.ge.f32 ph2, vh, %20;\n\t" \
        "setp.ge.f32 ph3, vh, %21;\n\t" \
        "@pl1 add.f32 %0, %0, x0;\n\t" \
        "@pl1 add.f32 %1, %1, y0;\n\t" \
        "@pl1 add.s32 %6, %6, %22;\n\t" \
        "@pl1 add.s32 %9, %9, 1;\n\t" \
        "@pl2 add.f32 %2, %2, x0;\n\t" \
        "@pl2 add.f32 %3, %3, y0;\n\t" \
        "@pl2 add.s32 %7, %7, %22;\n\t" \
        "@pl2 add.s32 %10, %10, 1;\n\t" \
        "@pl3 add.f32 %4, %4, x0;\n\t" \
        "@pl3 add.f32 %5, %5, y0;\n\t" \
        "@pl3 add.s32 %8, %8, %22;\n\t" \
        "@pl3 add.f32 %11, %11, 0F3F800000;\n\t" \
        "@ph1 add.f32 %0, %0, x1;\n\t" \
        "@ph1 add.f32 %1, %1, y1;\n\t" \
        "@ph1 add.s32 %6, %6, %23;\n\t" \
        "@ph1 add.s32 %9, %9, 1;\n\t" \
        "@ph2 add.f32 %2, %2, x1;\n\t" \
        "@ph2 add.f32 %3, %3, y1;\n\t" \
        "@ph2 add.s32 %7, %7, %23;\n\t" \
        "@ph2 add.s32 %10, %10, 1;\n\t" \
        "@ph3 add.f32 %4, %4, x1;\n\t" \
        "@ph3 add.f32 %5, %5, y1;\n\t" \
        "@ph3 add.s32 %8, %8, %23;\n\t" \
        "@ph3 add.f32 %11, %11, 0F3F800000;\n\t" \
        "}" \
        : "+f"(SX1), "+f"(SY1), "+f"(SX2), "+f"(SY2), "+f"(SX3), "+f"(SY3), \
          "+r"(AZ1), "+r"(AZ2), "+r"(AZ3), "+r"(AC1), "+r"(AC2), "+f"(FC3) \
        : "l"(XI2), "l"(YI2), "l"(ZI2), \
          "l"(x01), "l"(y01), "l"(z01), "l"(nu01), \
          "f"(TH1), "f"(TH2), "f"(TH3), \
          "r"(zf0), "r"(zf1))

// ---------------------------------------------------------------------------
// linear1: h = X_fea @ W1^T + b1 for all 4 iterations
// ---------------------------------------------------------------------------
__global__ void linear1_kernel(const float* __restrict__ Xfea,
                               const float* __restrict__ W1,
                               const float* __restrict__ b1) {
    int it = blockIdx.y;
    int n  = blockIdx.x * blockDim.x + threadIdx.x;
    __shared__ float sW[DF * DF];
    __shared__ float sb[DF];
    for (int k = threadIdx.x; k < DF * DF; k += blockDim.x) sW[k] = W1[it * DF * DF + k];
    if (threadIdx.x < DF) sb[threadIdx.x] = b1[it * DF + threadIdx.x];
    __syncthreads();
    if (n >= N) return;
    float xf[DF];
    const float4* xr = (const float4*)(Xfea + n * DF);
    #pragma unroll
    for (int q = 0; q < DF / 4; q++) {
        float4 v = xr[q];
        xf[4*q] = v.x; xf[4*q+1] = v.y; xf[4*q+2] = v.z; xf[4*q+3] = v.w;
    }
    float* hout = g_h + (it * N + n) * DF;
    #pragma unroll 4
    for (int f = 0; f < DF; f++) {
        float acc = sb[f];
        #pragma unroll
        for (int k = 0; k < DF; k++) acc = fmaf(xf[k], sW[f * DF + k], acc);
        hout[f] = acc;
    }
}

// BN stats + pair-record prep + counter reset (R13-proven).
__global__ void __launch_bounds__(1024, 1) bnstats_prep_kernel(const float* __restrict__ X) {
    int it = blockIdx.x;
    int tid = threadIdx.x;
    int w  = tid >> 5;
    int f  = tid & 31;
    float s = 0.f, sq = 0.f;
    for (int n = w; n < N; n += 32) {
        float v = g_h[(it * N + n) * DF + f];
        s += v;
        sq = fmaf(v, v, sq);
    }
    __shared__ float ss[32 * 33];
    __shared__ float sqq[32 * 33];
    ss [w * 33 + f] = s;
    sqq[w * 33 + f] = sq;
    __syncthreads();
    if (tid < DF) {
        float ts = 0.f, tq = 0.f;
        for (int ww = 0; ww < 32; ww++) { ts += ss[ww * 33 + f]; tq += sqq[ww * 33 + f]; }
        float mu  = ts / (float)N;
        float var = tq / (float)N - mu * mu;   // biased var (matches reference)
        g_stats[(it * DF + f) * 2 + 0] = mu;
        g_stats[(it * DF + f) * 2 + 1] = rsqrtf(var + 1e-5f);
    }
    int gtid = blockIdx.x * 1024 + tid;
    for (int sl = gtid; sl < NSLOTS_J; sl += 4096) {
        if (sl < N) write_rec(g_pairsA, sl, X[3*sl], X[3*sl+1], X[3*sl+2]);
        else        write_rec(g_pairsA, sl, SENTC, SENTC, SENTC);
        if (sl >= NSLOTS_I) write_rec(g_pairsB, sl, SENTC, SENTC, SENTC);
    }
    if (gtid < ITERS * NITILE) g_cnt[gtid] = 0;
}

// Wide-grid logits; ReLU folded inline (no a[] array -> low regs, high occ).
__global__ void logits_kernel(const float* __restrict__ gamma,
                              const float* __restrict__ beta,
                              const float* __restrict__ W2,
                              const float* __restrict__ b2) {
    int it = blockIdx.y;
    int n  = blockIdx.x * blockDim.x + threadIdx.x;
    __shared__ float sg[DF], sbe[DF], smu[DF], sis[DF], sW2[3 * DF], sb2[3];
    if (threadIdx.x < DF) {
        sg [threadIdx.x] = gamma[it * DF + threadIdx.x];
        sbe[threadIdx.x] = beta [it * DF + threadIdx.x];
        smu[threadIdx.x] = g_stats[(it * DF + threadIdx.x) * 2 + 0];
        sis[threadIdx.x] = g_stats[(it * DF + threadIdx.x) * 2 + 1];
    }
    if (threadIdx.x < 3 * DF) sW2[threadIdx.x] = W2[it * 3 * DF + threadIdx.x];
    if (threadIdx.x < 3)      sb2[threadIdx.x] = b2[it * 3 + threadIdx.x];
    __syncthreads();
    if (n >= N) return;
    const float* hrow = g_h + (it * N + n) * DF;
    float l0 = sb2[0], l1 = sb2[1], l2 = sb2[2];
    #pragma unroll 8
    for (int k = 0; k < DF; k++) {
        float a = fmaxf((hrow[k] - smu[k]) * sis[k] * sg[k] + sbe[k], 0.f);
        l0 = fmaf(a, sW2[0 * DF + k], l0);
        l1 = fmaf(a, sW2[1 * DF + k], l1);
        l2 = fmaf(a, sW2[2 * DF + k], l2);
    }
    float m = fmaxf(l0, fmaxf(l1, l2));
    float* wout = g_w + (it * N + n) * 3;
    wout[0] = expf(l0 - m);
    wout[1] = expf(l1 - m);
    wout[2] = expf(l2 - m);
}

// ---------------------------------------------------------------------------
// Mean-shift: 2 i-points per thread share each j-tile load. Fused finalize.
// ---------------------------------------------------------------------------
__global__ void __launch_bounds__(ITILE, 4) shift_kernel(float* __restrict__ out, int it) {
    __shared__ __align__(16) float sj[PCHUNK * 12];   // 8.8 KB tile
    __shared__ int s_last;

    const float* srcP = (it & 1) ? g_pairsB : g_pairsA;
    float*       dstP = (it & 1) ? g_pairsA : g_pairsB;

    int js  = blockIdx.y;
    int bx  = blockIdx.x;
    int tid = threadIdx.x;

    const float4* src = (const float4*)(srcP + js * PCHUNK * 12);
    float4* d4 = (float4*)sj;
    for (int t = tid; t < PCHUNK * 3; t += ITILE) d4[t] = src[t];
    __syncthreads();

    int slotA = bx * IBLK + tid;           // first i
    int slotB = slotA + ITILE;             // second i (same parity)
    int pbA = (slotA >> 1) * 12, hA = slotA & 1;
    int pbB = (slotB >> 1) * 12;
    float xiA  = srcP[pbA + 0 + hA], xiB  = srcP[pbB + 0 + hA];
    float yiA  = srcP[pbA + 2 + hA], yiB  = srcP[pbB + 2 + hA];
    float ziA  = srcP[pbA + 4 + hA], ziB  = srcP[pbB + 4 + hA];
    float nuiA = srcP[pbA + 6 + hA], nuiB = srcP[pbB + 6 + hA];
    float th1A = -nuiA - 0.02f,  th1B = -nuiB - 0.02f;    // bw=0.2
    float th2A = -nuiA - 1.445f, th2B = -nuiB - 1.445f;   // bw=1.7
    float th3A = -nuiA - 5.12f,  th3B = -nuiB - 5.12f;    // bw=3.2

    unsigned long long xi2A, yi2A, zi2A, xi2B, yi2B, zi2B;
    asm("mov.b64 %0, {%1, %1};" : "=l"(xi2A) : "f"(xiA));
    asm("mov.b64 %0, {%1, %1};" : "=l"(yi2A) : "f"(yiA));
    asm("mov.b64 %0, {%1, %1};" : "=l"(zi2A) : "f"(ziA));
    asm("mov.b64 %0, {%1, %1};" : "=l"(xi2B) : "f"(xiB));
    asm("mov.b64 %0, {%1, %1};" : "=l"(yi2B) : "f"(yiB));
    asm("mov.b64 %0, {%1, %1};" : "=l"(zi2B) : "f"(ziB));

    float sx1A=0,sy1A=0,sx2A=0,sy2A=0,sx3A=0,sy3A=0, fc3A=0;
    int   az1A=0,az2A=0,az3A=0, ac1A=0,ac2A=0;
    float sx1B=0,sy1B=0,sx2B=0,sy2B=0,sx3B=0,sy3B=0, fc3B=0;
    int   az1B=0,az2B=0,az3B=0, ac1B=0,ac2B=0;

    #pragma unroll 3
    for (int p = 0; p < PCHUNK; p++) {
        const float* rec = sj + p * 12;
        unsigned long long x01  = *(const unsigned long long*)(rec + 0);
        unsigned long long y01  = *(const unsigned long long*)(rec + 2);
        unsigned long long z01  = *(const unsigned long long*)(rec + 4);
        unsigned long long nu01 = *(const unsigned long long*)(rec + 6);
        unsigned long long zf01 = *(const unsigned long long*)(rec + 8);
        int zf0 = (int)(unsigned)zf01;
        int zf1 = (int)(zf01 >> 32);
        PAIR_ACC(sx1A,sy1A,sx2A,sy2A,sx3A,sy3A,az1A,az2A,az3A,ac1A,ac2A,fc3A,
                 xi2A,yi2A,zi2A,th1A,th2A,th3A);
        PAIR_ACC(sx1B,sy1B,sx2B,sy2B,sx3B,sy3B,az1B,az2B,az3B,ac1B,ac2B,fc3B,
                 xi2B,yi2B,zi2B,th1B,th2B,th3B);
    }

    float* dstA = g_part + (js * NSLOTS_I + slotA) * 12;
    ((float4*)dstA)[0] = make_float4(sx1A, sy1A, sx2A, sy2A);
    ((float4*)dstA)[1] = make_float4(sx3A, sy3A, __int_as_float(az1A), __int_as_float(az2A));
    ((float4*)dstA)[2] = make_float4(__int_as_float(az3A), __int_as_float(ac1A),
                                     __int_as_float(ac2A), fc3A);
    float* dstB = g_part + (js * NSLOTS_I + slotB) * 12;
    ((float4*)dstB)[0] = make_float4(sx1B, sy1B, sx2B, sy2B);
    ((float4*)dstB)[1] = make_float4(sx3B, sy3B, __int_as_float(az1B), __int_as_float(az2B));
    ((float4*)dstB)[2] = make_float4(__int_as_float(az3B), __int_as_float(ac1B),
                                     __int_as_float(ac2B), fc3B);

    // last-block finalize for this i-stripe (R8-proven protocol)
    __threadfence();
    __syncthreads();
    if (tid == 0) {
        int old = atomicAdd(&g_cnt[it * NITILE + bx], 1);
        s_last = (old == JSPLIT - 1) ? 1 : 0;
    }
    __syncthreads();
    if (!s_last) return;
    __threadfence();

    #pragma unroll
    for (int half = 0; half < IPT; half++) {
        int slot = bx * IBLK + half * ITILE + tid;
        float nx = SENTC, ny = SENTC, nz = SENTC;
        if (slot < N) {
            float sx1=0,sy1=0,sx2=0,sy2=0,sx3=0,sy3=0, c3=0.f;
            int   z1=0,z2=0,z3=0, c1=0,c2=0;
            #pragma unroll 2
            for (int js2 = 0; js2 < JSPLIT; js2++) {
                const float4* p = (const float4*)(g_part + (js2 * NSLOTS_I + slot) * 12);
                float4 v0 = p[0], v1 = p[1], v2 = p[2];
                sx1 += v0.x; sy1 += v0.y; sx2 += v0.z; sy2 += v0.w;
                sx3 += v1.x; sy3 += v1.y;
                z1 += __float_as_int(v1.z); z2 += __float_as_int(v1.w);
                z3 += __float_as_int(v2.x);
                c1 += __float_as_int(v2.y); c2 += __float_as_int(v2.z); c3 += v2.w;
            }
            float sz1 = (float)z1 * (1.0f / ZSCALE);
            float sz2 = (float)z2 * (1.0f / ZSCALE);
            float sz3 = (float)z3 * (1.0f / ZSCALE);
            const float* wp = g_w + (it * N + slot) * 3;
            float e0 = wp[0], e1 = wp[1], e2 = wp[2];
            float inv = 1.0f / (e0 + e1 + e2);
            float r1 = e0 / (float)c1, r2 = e1 / (float)c2, r3 = e2 / c3;
            nx = (sx1 * r1 + sx2 * r2 + sx3 * r3) * inv;
            ny = (sy1 * r1 + sy2 * r2 + sy3 * r3) * inv;
            nz = (sz1 * r1 + sz2 * r2 + sz3 * r3) * inv;
            float* oo = out + (it * N + slot) * 3;
            oo[0] = nx; oo[1] = ny; oo[2] = nz;
        }
        if (it < ITERS - 1) write_rec(dstP, slot, nx, ny, nz);
    }
}

// ---------------------------------------------------------------------------
// Inputs: 0:X 1:X_fea 2:W1 3:b1 4:gamma 5:beta 6:W2 7:b2   Output: [4,N,3] f32
// 7 launches; shift(it=0) at index 3 (ncu capture point).
// ---------------------------------------------------------------------------
extern "C" void kernel_launch(void* const* d_in, const int* in_sizes, int n_in,
                              void* d_out, int out_size) {
    const float* X     = (const float*)d_in[0];
    const float* Xfea  = (const float*)d_in[1];
    const float* W1    = (const float*)d_in[2];
    const float* b1    = (const float*)d_in[3];
    const float* gamma = (const float*)d_in[4];
    const float* beta  = (const float*)d_in[5];
    const float* W2    = (const float*)d_in[6];
    const float* b2    = (const float*)d_in[7];
    float* out = (float*)d_out;

    linear1_kernel<<<dim3((N + 127) / 128, ITERS), 128>>>(Xfea, W1, b1);        // 0
    bnstats_prep_kernel<<<ITERS, 1024>>>(X);                                     // 1
    logits_kernel<<<dim3((N + 255) / 256, ITERS), 256>>>(gamma, beta, W2, b2);   // 2
    for (int it = 0; it < ITERS; it++)                                           // 3..6
        shift_kernel<<<dim3(NITILE, JSPLIT), ITILE>>>(out, it);
}

// round 16
// speedup vs baseline: 1.0688x; 1.0688x over previous
#include <cuda_runtime.h>
#include <math.h>

// Problem constants
#define N        10000
#define DF       32
#define ITERS    4
#define JSPLIT   22             // j-range splits
#define PCHUNK   233            // packed j-pairs per split (466 j)
#define NPAIR_PAD (JSPLIT * PCHUNK)    // 5126 pairs = 10252 j slots
#define NSLOTS_J (2 * NPAIR_PAD)       // 10252
#define ITILE    256            // threads per block
#define IPT      2              // i-points per thread
#define IBLK     (ITILE * IPT)  // 512 i per block
#define NITILE   20             // i-slots 10240; grid 20*22 = 440 <= 444 @ occ 3
#define NSLOTS_I 10240
#define ZSCALE   16384.0f
#define SENTC    1.0e6f

// Scratch (static device arrays; cudaMalloc is forbidden)
__device__ float g_pairsA[NPAIR_PAD * 12];
__device__ float g_pairsB[NPAIR_PAD * 12];
__device__ int   g_cnt[ITERS * NITILE];        // stripe completion counters
__device__ float g_part[JSPLIT * NSLOTS_I * 12];
__device__ float g_h[ITERS * N * DF];
__device__ float g_stats[ITERS * DF * 2];
__device__ float g_w[ITERS * N * 3];

// ---------------------------------------------------------------------------
// Pair record (12 words per packed j-pair):
//   [0..7]  x0 x1 y0 y1 z0 z1 nu0 nu1   (nu = -0.5|x|^2; also the addends)
//   [8,9]   round(z*2^14) s32 (zf0, zf1)
//   [10,11] pad
// ---------------------------------------------------------------------------
__device__ __forceinline__ void write_rec(float* buf, int s, float x, float y, float z) {
    int p = s >> 1, h = s & 1;
    float nu = -0.5f * (x * x + y * y + z * z);
    float* rec = buf + p * 12;
    rec[0 + h] = x;
    rec[2 + h] = y;
    rec[4 + h] = z;
    rec[6 + h] = nu;
    ((int*)rec)[8 + h] = __float2int_rn(z * ZSCALE);
}

// Per-pair accumulate for one i-point. Distance chain verified against R13:
//   t64 = xi*x01 + nu01;  t64 += yi*y01;  t64 += zi*z01
// (%15=x01, %16=y01, %17=z01, %18=nu01)
#define PAIR_ACC(SX1,SY1,SX2,SY2,SX3,SY3,AZ1,AZ2,AZ3,AC1,AC2,FC3,XI2,YI2,ZI2,TH1,TH2,TH3) \
    asm("{\n\t" \
        ".reg .b64  t64;\n\t" \
        ".reg .f32  vl, vh;\n\t" \
        ".reg .pred pl1, pl2, pl3, ph1, ph2, ph3;\n\t" \
        "fma.rn.f32x2 t64, %12, %15, %18;\n\t" \
        "fma.rn.f32x2 t64, %13, %16, t64;\n\t" \
        "fma.rn.f32x2 t64, %14, %17, t64;\n\t" \
        "mov.b64 {vl, vh}, t64;\n\t" \
        "setp.ge.f32 pl1, vl, %19;\n\t" \
        "setp.ge.f32 pl2, vl, %20;\n\t" \
        "setp.ge.f32 pl3, vl, %21;\n\t" \
        "setp.ge.f32 ph1, vh, %19;\n\t" \
        "setp.ge.f32 ph2, vh, %20;\n\t" \
        "setp.ge.f32 ph3, vh, %21;\n\t" \
        "@pl1 add.f32 %0, %0, %24;\n\t" \
        "@pl1 add.f32 %1, %1, %26;\n\t" \
        "@pl1 add.s32 %6, %6, %22;\n\t" \
        "@pl1 add.s32 %9, %9, 1;\n\t" \
        "@pl2 add.f32 %2, %2, %24;\n\t" \
        "@pl2 add.f32 %3, %3, %26;\n\t" \
        "@pl2 add.s32 %7, %7, %22;\n\t" \
        "@pl2 add.s32 %10, %10, 1;\n\t" \
        "@pl3 add.f32 %4, %4, %24;\n\t" \
        "@pl3 add.f32 %5, %5, %26;\n\t" \
        "@pl3 add.s32 %8, %8, %22;\n\t" \
        "@pl3 add.f32 %11, %11, 0F3F800000;\n\t" \
        "@ph1 add.f32 %0, %0, %25;\n\t" \
        "@ph1 add.f32 %1, %1, %27;\n\t" \
        "@ph1 add.s32 %6, %6, %23;\n\t" \
        "@ph1 add.s32 %9, %9, 1;\n\t" \
        "@ph2 add.f32 %2, %2, %25;\n\t" \
        "@ph2 add.f32 %3, %3, %27;\n\t" \
        "@ph2 add.s32 %7, %7, %23;\n\t" \
        "@ph2 add.s32 %10, %10, 1;\n\t" \
        "@ph3 add.f32 %4, %4, %25;\n\t" \
        "@ph3 add.f32 %5, %5, %27;\n\t" \
        "@ph3 add.s32 %8, %8, %23;\n\t" \
        "@ph3 add.f32 %11, %11, 0F3F800000;\n\t" \
        "}" \
        : "+f"(SX1), "+f"(SY1), "+f"(SX2), "+f"(SY2), "+f"(SX3), "+f"(SY3), \
          "+r"(AZ1), "+r"(AZ2), "+r"(AZ3), "+r"(AC1), "+r"(AC2), "+f"(FC3) \
        : "l"(XI2), "l"(YI2), "l"(ZI2), \
          "l"(x01), "l"(y01), "l"(z01), "l"(nu01), \
          "f"(TH1), "f"(TH2), "f"(TH3), \
          "r"(zf0), "r"(zf1), \
          "f"(jx0), "f"(jx1), "f"(jy0), "f"(jy1))

// ---------------------------------------------------------------------------
// linear1: h = X_fea @ W1^T + b1 for all 4 iterations
// ---------------------------------------------------------------------------
__global__ void linear1_kernel(const float* __restrict__ Xfea,
                               const float* __restrict__ W1,
                               const float* __restrict__ b1) {
    int it = blockIdx.y;
    int n  = blockIdx.x * blockDim.x + threadIdx.x;
    __shared__ float sW[DF * DF];
    __shared__ float sb[DF];
    for (int k = threadIdx.x; k < DF * DF; k += blockDim.x) sW[k] = W1[it * DF * DF + k];
    if (threadIdx.x < DF) sb[threadIdx.x] = b1[it * DF + threadIdx.x];
    __syncthreads();
    if (n >= N) return;
    float xf[DF];
    const float4* xr = (const float4*)(Xfea + n * DF);
    #pragma unroll
    for (int q = 0; q < DF / 4; q++) {
        float4 v = xr[q];
        xf[4*q] = v.x; xf[4*q+1] = v.y; xf[4*q+2] = v.z; xf[4*q+3] = v.w;
    }
    float* hout = g_h + (it * N + n) * DF;
    #pragma unroll 4
    for (int f = 0; f < DF; f++) {
        float acc = sb[f];
        #pragma unroll
        for (int k = 0; k < DF; k++) acc = fmaf(xf[k], sW[f * DF + k], acc);
        hout[f] = acc;
    }
}

// BN stats + pair-record prep + counter reset (R13-proven).
__global__ void __launch_bounds__(1024, 1) bnstats_prep_kernel(const float* __restrict__ X) {
    int it = blockIdx.x;
    int tid = threadIdx.x;
    int w  = tid >> 5;
    int f  = tid & 31;
    float s = 0.f, sq = 0.f;
    for (int n = w; n < N; n += 32) {
        float v = g_h[(it * N + n) * DF + f];
        s += v;
        sq = fmaf(v, v, sq);
    }
    __shared__ float ss[32 * 33];
    __shared__ float sqq[32 * 33];
    ss [w * 33 + f] = s;
    sqq[w * 33 + f] = sq;
    __syncthreads();
    if (tid < DF) {
        float ts = 0.f, tq = 0.f;
        for (int ww = 0; ww < 32; ww++) { ts += ss[ww * 33 + f]; tq += sqq[ww * 33 + f]; }
        float mu  = ts / (float)N;
        float var = tq / (float)N - mu * mu;   // biased var (matches reference)
        g_stats[(it * DF + f) * 2 + 0] = mu;
        g_stats[(it * DF + f) * 2 + 1] = rsqrtf(var + 1e-5f);
    }
    int gtid = blockIdx.x * 1024 + tid;
    for (int sl = gtid; sl < NSLOTS_J; sl += 4096) {
        if (sl < N) write_rec(g_pairsA, sl, X[3*sl], X[3*sl+1], X[3*sl+2]);
        else        write_rec(g_pairsA, sl, SENTC, SENTC, SENTC);
        if (sl >= NSLOTS_I) write_rec(g_pairsB, sl, SENTC, SENTC, SENTC);
    }
    if (gtid < ITERS * NITILE) g_cnt[gtid] = 0;
}

// Wide-grid logits; ReLU folded inline (low regs, high occ).
__global__ void logits_kernel(const float* __restrict__ gamma,
                              const float* __restrict__ beta,
                              const float* __restrict__ W2,
                              const float* __restrict__ b2) {
    int it = blockIdx.y;
    int n  = blockIdx.x * blockDim.x + threadIdx.x;
    __shared__ float sg[DF], sbe[DF], smu[DF], sis[DF], sW2[3 * DF], sb2[3];
    if (threadIdx.x < DF) {
        sg [threadIdx.x] = gamma[it * DF + threadIdx.x];
        sbe[threadIdx.x] = beta [it * DF + threadIdx.x];
        smu[threadIdx.x] = g_stats[(it * DF + threadIdx.x) * 2 + 0];
        sis[threadIdx.x] = g_stats[(it * DF + threadIdx.x) * 2 + 1];
    }
    if (threadIdx.x < 3 * DF) sW2[threadIdx.x] = W2[it * 3 * DF + threadIdx.x];
    if (threadIdx.x < 3)      sb2[threadIdx.x] = b2[it * 3 + threadIdx.x];
    __syncthreads();
    if (n >= N) return;
    const float* hrow = g_h + (it * N + n) * DF;
    float l0 = sb2[0], l1 = sb2[1], l2 = sb2[2];
    #pragma unroll 8
    for (int k = 0; k < DF; k++) {
        float a = fmaxf((hrow[k] - smu[k]) * sis[k] * sg[k] + sbe[k], 0.f);
        l0 = fmaf(a, sW2[0 * DF + k], l0);
        l1 = fmaf(a, sW2[1 * DF + k], l1);
        l2 = fmaf(a, sW2[2 * DF + k], l2);
    }
    float m = fmaxf(l0, fmaxf(l1, l2));
    float* wout = g_w + (it * N + n) * 3;
    wout[0] = expf(l0 - m);
    wout[1] = expf(l1 - m);
    wout[2] = expf(l2 - m);
}

// ---------------------------------------------------------------------------
// Mean-shift: 2 i-points per thread share each j-load; occ 3 frees registers.
// ---------------------------------------------------------------------------
__global__ void __launch_bounds__(ITILE, 3) shift_kernel(float* __restrict__ out, int it) {
    __shared__ __align__(16) float sj[PCHUNK * 12];   // 11.2 KB tile
    __shared__ int s_last;

    const float* srcP = (it & 1) ? g_pairsB : g_pairsA;
    float*       dstP = (it & 1) ? g_pairsA : g_pairsB;

    int js  = blockIdx.y;
    int bx  = blockIdx.x;
    int tid = threadIdx.x;

    const float4* src = (const float4*)(srcP + js * PCHUNK * 12);
    float4* d4 = (float4*)sj;
    for (int t = tid; t < PCHUNK * 3; t += ITILE) d4[t] = src[t];
    __syncthreads();

    int slotA = bx * IBLK + tid;           // first i
    int slotB = slotA + ITILE;             // second i (same parity)
    int pbA = (slotA >> 1) * 12, hA = slotA & 1;
    int pbB = (slotB >> 1) * 12;
    float xiA  = srcP[pbA + 0 + hA], xiB  = srcP[pbB + 0 + hA];
    float yiA  = srcP[pbA + 2 + hA], yiB  = srcP[pbB + 2 + hA];
    float ziA  = srcP[pbA + 4 + hA], ziB  = srcP[pbB + 4 + hA];
    float nuiA = srcP[pbA + 6 + hA], nuiB = srcP[pbB + 6 + hA];
    float th1A = -nuiA - 0.02f,  th1B = -nuiB - 0.02f;    // bw=0.2
    float th2A = -nuiA - 1.445f, th2B = -nuiB - 1.445f;   // bw=1.7
    float th3A = -nuiA - 5.12f,  th3B = -nuiB - 5.12f;    // bw=3.2

    unsigned long long xi2A, yi2A, zi2A, xi2B, yi2B, zi2B;
    asm("mov.b64 %0, {%1, %1};" : "=l"(xi2A) : "f"(xiA));
    asm("mov.b64 %0, {%1, %1};" : "=l"(yi2A) : "f"(yiA));
    asm("mov.b64 %0, {%1, %1};" : "=l"(zi2A) : "f"(ziA));
    asm("mov.b64 %0, {%1, %1};" : "=l"(xi2B) : "f"(xiB));
    asm("mov.b64 %0, {%1, %1};" : "=l"(yi2B) : "f"(yiB));
    asm("mov.b64 %0, {%1, %1};" : "=l"(zi2B) : "f"(ziB));

    float sx1A=0,sy1A=0,sx2A=0,sy2A=0,sx3A=0,sy3A=0, fc3A=0;
    int   az1A=0,az2A=0,az3A=0, ac1A=0,ac2A=0;
    float sx1B=0,sy1B=0,sx2B=0,sy2B=0,sx3B=0,sy3B=0, fc3B=0;
    int   az1B=0,az2B=0,az3B=0, ac1B=0,ac2B=0;

    #pragma unroll 2
    for (int p = 0; p < PCHUNK; p++) {
        const float* rec = sj + p * 12;
        unsigned long long x01  = *(const unsigned long long*)(rec + 0);
        unsigned long long y01  = *(const unsigned long long*)(rec + 2);
        unsigned long long z01  = *(const unsigned long long*)(rec + 4);
        unsigned long long nu01 = *(const unsigned long long*)(rec + 6);
        unsigned long long zf01 = *(const unsigned long long*)(rec + 8);
        int zf0 = (int)(unsigned)zf01;
        int zf1 = (int)(zf01 >> 32);
        // hoisted i-independent unpacks (once per pair, shared by both evals)
        float jx0 = __uint_as_float((unsigned)x01);
        float jx1 = __uint_as_float((unsigned)(x01 >> 32));
        float jy0 = __uint_as_float((unsigned)y01);
        float jy1 = __uint_as_float((unsigned)(y01 >> 32));
        PAIR_ACC(sx1A,sy1A,sx2A,sy2A,sx3A,sy3A,az1A,az2A,az3A,ac1A,ac2A,fc3A,
                 xi2A,yi2A,zi2A,th1A,th2A,th3A);
        PAIR_ACC(sx1B,sy1B,sx2B,sy2B,sx3B,sy3B,az1B,az2B,az3B,ac1B,ac2B,fc3B,
                 xi2B,yi2B,zi2B,th1B,th2B,th3B);
    }

    float* dstA = g_part + (js * NSLOTS_I + slotA) * 12;
    ((float4*)dstA)[0] = make_float4(sx1A, sy1A, sx2A, sy2A);
    ((float4*)dstA)[1] = make_float4(sx3A, sy3A, __int_as_float(az1A), __int_as_float(az2A));
    ((float4*)dstA)[2] = make_float4(__int_as_float(az3A), __int_as_float(ac1A),
                                     __int_as_float(ac2A), fc3A);
    float* dstB = g_part + (js * NSLOTS_I + slotB) * 12;
    ((float4*)dstB)[0] = make_float4(sx1B, sy1B, sx2B, sy2B);
    ((float4*)dstB)[1] = make_float4(sx3B, sy3B, __int_as_float(az1B), __int_as_float(az2B));
    ((float4*)dstB)[2] = make_float4(__int_as_float(az3B), __int_as_float(ac1B),
                                     __int_as_float(ac2B), fc3B);

    // last-block finalize for this i-stripe (R8-proven protocol)
    __threadfence();
    __syncthreads();
    if (tid == 0) {
        int old = atomicAdd(&g_cnt[it * NITILE + bx], 1);
        s_last = (old == JSPLIT - 1) ? 1 : 0;
    }
    __syncthreads();
    if (!s_last) return;
    __threadfence();

    #pragma unroll
    for (int half = 0; half < IPT; half++) {
        int slot = bx * IBLK + half * ITILE + tid;
        float nx = SENTC, ny = SENTC, nz = SENTC;
        if (slot < N) {
            float sx1=0,sy1=0,sx2=0,sy2=0,sx3=0,sy3=0, c3=0.f;
            int   z1=0,z2=0,z3=0, c1=0,c2=0;
            #pragma unroll 2
            for (int js2 = 0; js2 < JSPLIT; js2++) {
                const float4* p = (const float4*)(g_part + (js2 * NSLOTS_I + slot) * 12);
                float4 v0 = p[0], v1 = p[1], v2 = p[2];
                sx1 += v0.x; sy1 += v0.y; sx2 += v0.z; sy2 += v0.w;
                sx3 += v1.x; sy3 += v1.y;
                z1 += __float_as_int(v1.z); z2 += __float_as_int(v1.w);
                z3 += __float_as_int(v2.x);
                c1 += __float_as_int(v2.y); c2 += __float_as_int(v2.z); c3 += v2.w;
            }
            float sz1 = (float)z1 * (1.0f / ZSCALE);
            float sz2 = (float)z2 * (1.0f / ZSCALE);
            float sz3 = (float)z3 * (1.0f / ZSCALE);
            const float* wp = g_w + (it * N + slot) * 3;
            float e0 = wp[0], e1 = wp[1], e2 = wp[2];
            float inv = 1.0f / (e0 + e1 + e2);
            float r1 = e0 / (float)c1, r2 = e1 / (float)c2, r3 = e2 / c3;
            nx = (sx1 * r1 + sx2 * r2 + sx3 * r3) * inv;
            ny = (sy1 * r1 + sy2 * r2 + sy3 * r3) * inv;
            nz = (sz1 * r1 + sz2 * r2 + sz3 * r3) * inv;
            float* oo = out + (it * N + slot) * 3;
            oo[0] = nx; oo[1] = ny; oo[2] = nz;
        }
        if (it < ITERS - 1) write_rec(dstP, slot, nx, ny, nz);
    }
}

// ---------------------------------------------------------------------------
// Inputs: 0:X 1:X_fea 2:W1 3:b1 4:gamma 5:beta 6:W2 7:b2   Output: [4,N,3] f32
// 7 launches; shift(it=0) at index 3 (ncu capture point).
// ---------------------------------------------------------------------------
extern "C" void kernel_launch(void* const* d_in, const int* in_sizes, int n_in,
                              void* d_out, int out_size) {
    const float* X     = (const float*)d_in[0];
    const float* Xfea  = (const float*)d_in[1];
    const float* W1    = (const float*)d_in[2];
    const float* b1    = (const float*)d_in[3];
    const float* gamma = (const float*)d_in[4];
    const float* beta  = (const float*)d_in[5];
    const float* W2    = (const float*)d_in[6];
    const float* b2    = (const float*)d_in[7];
    float* out = (float*)d_out;

    linear1_kernel<<<dim3((N + 127) / 128, ITERS), 128>>>(Xfea, W1, b1);        // 0
    bnstats_prep_kernel<<<ITERS, 1024>>>(X);                                     // 1
    logits_kernel<<<dim3((N + 255) / 256, ITERS), 256>>>(gamma, beta, W2, b2);   // 2
    for (int it = 0; it < ITERS; it++)                                           // 3..6
        shift_kernel<<<dim3(NITILE, JSPLIT), ITILE>>>(out, it);
}

// round 17
// speedup vs baseline: 1.1560x; 1.0815x over previous
#include <cuda_runtime.h>
#include <math.h>

// Problem constants
#define N        10000
#define DF       32
#define ITERS    4
#define JSPLIT   14             // j-range splits
#define PCHUNK   366            // packed j-pairs per split (732 j), 6*61
#define NPAIR_PAD (JSPLIT * PCHUNK)    // 5124 pairs = 10248 j slots
#define NSLOTS_J (2 * NPAIR_PAD)       // 10248
#define ITILE    256
#define NITILE   40             // i-slots 10240; grid 40*14 = 560, 1 wave @ occ 4
#define NSLOTS_I 10240
#define ZSCALE   16384.0f
#define SENTC    1.0e6f

// Scratch (static device arrays; cudaMalloc is forbidden)
__device__ float g_pairsA[NPAIR_PAD * 12];
__device__ float g_pairsB[NPAIR_PAD * 12];
__device__ int   g_cnt[ITERS * NITILE];        // stripe completion counters
__device__ float g_part[JSPLIT * NSLOTS_I * 12];
__device__ float g_h[ITERS * N * DF];
__device__ float g_stats[ITERS * DF * 2];
__device__ float g_w[ITERS * N * 3];

// ---------------------------------------------------------------------------
// Pair record (12 words per packed j-pair):
//   [0..7]  x0 x1 y0 y1 z0 z1 nu0 nu1   (nu = -0.5|x|^2; also the addends)
//   [8,9]   round(z*2^14) s32 (zf0, zf1)
//   [10,11] pad (never read)
// ---------------------------------------------------------------------------
__device__ __forceinline__ void write_rec(float* buf, int s, float x, float y, float z) {
    int p = s >> 1, h = s & 1;
    float nu = -0.5f * (x * x + y * y + z * z);
    float* rec = buf + p * 12;
    rec[0 + h] = x;
    rec[2 + h] = y;
    rec[4 + h] = z;
    rec[6 + h] = nu;
    ((int*)rec)[8 + h] = __float2int_rn(z * ZSCALE);
}

// ---------------------------------------------------------------------------
// linear1: h = X_fea @ W1^T + b1 for all 4 iterations
// ---------------------------------------------------------------------------
__global__ void linear1_kernel(const float* __restrict__ Xfea,
                               const float* __restrict__ W1,
                               const float* __restrict__ b1) {
    int it = blockIdx.y;
    int n  = blockIdx.x * blockDim.x + threadIdx.x;
    __shared__ float sW[DF * DF];
    __shared__ float sb[DF];
    for (int k = threadIdx.x; k < DF * DF; k += blockDim.x) sW[k] = W1[it * DF * DF + k];
    if (threadIdx.x < DF) sb[threadIdx.x] = b1[it * DF + threadIdx.x];
    __syncthreads();
    if (n >= N) return;
    float xf[DF];
    const float4* xr = (const float4*)(Xfea + n * DF);
    #pragma unroll
    for (int q = 0; q < DF / 4; q++) {
        float4 v = xr[q];
        xf[4*q] = v.x; xf[4*q+1] = v.y; xf[4*q+2] = v.z; xf[4*q+3] = v.w;
    }
    float* hout = g_h + (it * N + n) * DF;
    #pragma unroll 4
    for (int f = 0; f < DF; f++) {
        float acc = sb[f];
        #pragma unroll
        for (int k = 0; k < DF; k++) acc = fmaf(xf[k], sW[f * DF + k], acc);
        hout[f] = acc;
    }
}

// BN stats + pair-record prep + counter reset (R13-proven).
__global__ void __launch_bounds__(1024, 1) bnstats_prep_kernel(const float* __restrict__ X) {
    int it = blockIdx.x;
    int tid = threadIdx.x;
    int w  = tid >> 5;
    int f  = tid & 31;
    float s = 0.f, sq = 0.f;
    for (int n = w; n < N; n += 32) {
        float v = g_h[(it * N + n) * DF + f];
        s += v;
        sq = fmaf(v, v, sq);
    }
    __shared__ float ss[32 * 33];
    __shared__ float sqq[32 * 33];
    ss [w * 33 + f] = s;
    sqq[w * 33 + f] = sq;
    __syncthreads();
    if (tid < DF) {
        float ts = 0.f, tq = 0.f;
        for (int ww = 0; ww < 32; ww++) { ts += ss[ww * 33 + f]; tq += sqq[ww * 33 + f]; }
        float mu  = ts / (float)N;
        float var = tq / (float)N - mu * mu;   // biased var (matches reference)
        g_stats[(it * DF + f) * 2 + 0] = mu;
        g_stats[(it * DF + f) * 2 + 1] = rsqrtf(var + 1e-5f);
    }
    int gtid = blockIdx.x * 1024 + tid;
    for (int sl = gtid; sl < NSLOTS_J; sl += 4096) {
        if (sl < N) write_rec(g_pairsA, sl, X[3*sl], X[3*sl+1], X[3*sl+2]);
        else        write_rec(g_pairsA, sl, SENTC, SENTC, SENTC);
        if (sl >= NSLOTS_I) write_rec(g_pairsB, sl, SENTC, SENTC, SENTC);
    }
    if (gtid < ITERS * NITILE) g_cnt[gtid] = 0;
}

// Wide-grid logits; ReLU folded inline (R16-verified: low regs, high occ).
__global__ void logits_kernel(const float* __restrict__ gamma,
                              const float* __restrict__ beta,
                              const float* __restrict__ W2,
                              const float* __restrict__ b2) {
    int it = blockIdx.y;
    int n  = blockIdx.x * blockDim.x + threadIdx.x;
    __shared__ float sg[DF], sbe[DF], smu[DF], sis[DF], sW2[3 * DF], sb2[3];
    if (threadIdx.x < DF) {
        sg [threadIdx.x] = gamma[it * DF + threadIdx.x];
        sbe[threadIdx.x] = beta [it * DF + threadIdx.x];
        smu[threadIdx.x] = g_stats[(it * DF + threadIdx.x) * 2 + 0];
        sis[threadIdx.x] = g_stats[(it * DF + threadIdx.x) * 2 + 1];
    }
    if (threadIdx.x < 3 * DF) sW2[threadIdx.x] = W2[it * 3 * DF + threadIdx.x];
    if (threadIdx.x < 3)      sb2[threadIdx.x] = b2[it * 3 + threadIdx.x];
    __syncthreads();
    if (n >= N) return;
    const float* hrow = g_h + (it * N + n) * DF;
    float l0 = sb2[0], l1 = sb2[1], l2 = sb2[2];
    #pragma unroll 8
    for (int k = 0; k < DF; k++) {
        float a = fmaxf((hrow[k] - smu[k]) * sis[k] * sg[k] + sbe[k], 0.f);
        l0 = fmaf(a, sW2[0 * DF + k], l0);
        l1 = fmaf(a, sW2[1 * DF + k], l1);
        l2 = fmaf(a, sW2[2 * DF + k], l2);
    }
    float m = fmaxf(l0, fmaxf(l1, l2));
    float* wout = g_w + (it * N + n) * 3;
    wout[0] = expf(l0 - m);
    wout[1] = expf(l1 - m);
    wout[2] = expf(l2 - m);
}

// ---------------------------------------------------------------------------
// Mean-shift pair loop (R13 body byte-for-byte, unroll 6) + fused finalize.
// ---------------------------------------------------------------------------
__global__ void __launch_bounds__(ITILE, 4) shift_kernel(float* __restrict__ out, int it) {
    __shared__ __align__(16) float sj[PCHUNK * 12];   // 17.6 KB tile
    __shared__ int s_last;

    const float* srcP = (it & 1) ? g_pairsB : g_pairsA;
    float*       dstP = (it & 1) ? g_pairsA : g_pairsB;

    int js  = blockIdx.y;
    int bx  = blockIdx.x;
    int tid = threadIdx.x;

    const float4* src = (const float4*)(srcP + js * PCHUNK * 12);
    float4* d4 = (float4*)sj;
    for (int t = tid; t < PCHUNK * 3; t += ITILE) d4[t] = src[t];
    __syncthreads();

    int slot = bx * ITILE + tid;     // < NSLOTS_I
    int pb = (slot >> 1) * 12, h = slot & 1;
    float xi  = srcP[pb + 0 + h];
    float yi  = srcP[pb + 2 + h];
    float zi  = srcP[pb + 4 + h];
    float nui = srcP[pb + 6 + h];
    // d <= bw^2  <=>  (xi.xj - 0.5|xj|^2) >= 0.5|xi|^2 - 0.5 bw^2
    float th1 = -nui - 0.02f;    // bw=0.2
    float th2 = -nui - 1.445f;   // bw=1.7
    float th3 = -nui - 5.12f;    // bw=3.2

    unsigned long long xi2, yi2, zi2;
    asm("mov.b64 %0, {%1, %1};" : "=l"(xi2) : "f"(xi));
    asm("mov.b64 %0, {%1, %1};" : "=l"(yi2) : "f"(yi));
    asm("mov.b64 %0, {%1, %1};" : "=l"(zi2) : "f"(zi));

    float sx1 = 0.f, sy1 = 0.f, sx2 = 0.f, sy2 = 0.f, sx3 = 0.f, sy3 = 0.f;
    int   az1 = 0, az2 = 0, az3 = 0;      // fixed-point z sums
    int   ac1 = 0, ac2 = 0;               // counts bands 1,2 (alu)
    float fc3 = 0.0f;                     // count band 3 (fma)

    #pragma unroll 6
    for (int p = 0; p < PCHUNK; p++) {
        const float* rec = sj + p * 12;
        unsigned long long x01  = *(const unsigned long long*)(rec + 0);
        unsigned long long y01  = *(const unsigned long long*)(rec + 2);
        unsigned long long z01  = *(const unsigned long long*)(rec + 4);
        unsigned long long nu01 = *(const unsigned long long*)(rec + 6);
        unsigned long long zf01 = *(const unsigned long long*)(rec + 8);
        int zf0 = (int)(unsigned)zf01;
        int zf1 = (int)(zf01 >> 32);
        asm("{\n\t"
            ".reg .b64  t64;\n\t"
            ".reg .f32  vl, vh, x0, x1, y0, y1;\n\t"
            ".reg .pred pl1, pl2, pl3, ph1, ph2, ph3;\n\t"
            "fma.rn.f32x2 t64, %12, %15, %18;\n\t"   // xi*xj - 0.5|xj|^2
            "fma.rn.f32x2 t64, %13, %16, t64;\n\t"
            "fma.rn.f32x2 t64, %14, %17, t64;\n\t"
            "mov.b64 {vl, vh}, t64;\n\t"
            "mov.b64 {x0, x1}, %15;\n\t"
            "mov.b64 {y0, y1}, %16;\n\t"
            "setp.ge.f32 pl1, vl, %19;\n\t"
            "setp.ge.f32 pl2, vl, %20;\n\t"
            "setp.ge.f32 pl3, vl, %21;\n\t"
            "setp.ge.f32 ph1, vh, %19;\n\t"
            "setp.ge.f32 ph2, vh, %20;\n\t"
            "setp.ge.f32 ph3, vh, %21;\n\t"
            "@pl1 add.f32 %0, %0, x0;\n\t"
            "@pl1 add.f32 %1, %1, y0;\n\t"
            "@pl1 add.s32 %6, %6, %22;\n\t"
            "@pl1 add.s32 %9, %9, 1;\n\t"
            "@pl2 add.f32 %2, %2, x0;\n\t"
            "@pl2 add.f32 %3, %3, y0;\n\t"
            "@pl2 add.s32 %7, %7, %22;\n\t"
            "@pl2 add.s32 %10, %10, 1;\n\t"
            "@pl3 add.f32 %4, %4, x0;\n\t"
            "@pl3 add.f32 %5, %5, y0;\n\t"
            "@pl3 add.s32 %8, %8, %22;\n\t"
            "@pl3 add.f32 %11, %11, 0F3F800000;\n\t"
            "@ph1 add.f32 %0, %0, x1;\n\t"
            "@ph1 add.f32 %1, %1, y1;\n\t"
            "@ph1 add.s32 %6, %6, %23;\n\t"
            "@ph1 add.s32 %9, %9, 1;\n\t"
            "@ph2 add.f32 %2, %2, x1;\n\t"
            "@ph2 add.f32 %3, %3, y1;\n\t"
            "@ph2 add.s32 %7, %7, %23;\n\t"
            "@ph2 add.s32 %10, %10, 1;\n\t"
            "@ph3 add.f32 %4, %4, x1;\n\t"
            "@ph3 add.f32 %5, %5, y1;\n\t"
            "@ph3 add.s32 %8, %8, %23;\n\t"
            "@ph3 add.f32 %11, %11, 0F3F800000;\n\t"
            "}"
            : "+f"(sx1), "+f"(sy1), "+f"(sx2), "+f"(sy2), "+f"(sx3), "+f"(sy3),
              "+r"(az1), "+r"(az2), "+r"(az3),
              "+r"(ac1), "+r"(ac2), "+f"(fc3)
            : "l"(xi2), "l"(yi2), "l"(zi2),
              "l"(x01), "l"(y01), "l"(z01), "l"(nu01),
              "f"(th1), "f"(th2), "f"(th3),
              "r"(zf0), "r"(zf1));
    }

    float* dst = g_part + (js * NSLOTS_I + slot) * 12;
    ((float4*)dst)[0] = make_float4(sx1, sy1, sx2, sy2);
    ((float4*)dst)[1] = make_float4(sx3, sy3, __int_as_float(az1), __int_as_float(az2));
    ((float4*)dst)[2] = make_float4(__int_as_float(az3), __int_as_float(ac1),
                                    __int_as_float(ac2), fc3);

    // last-block finalize for this i-stripe (R8-proven protocol)
    __threadfence();
    __syncthreads();
    if (tid == 0) {
        int old = atomicAdd(&g_cnt[it * NITILE + bx], 1);
        s_last = (old == JSPLIT - 1) ? 1 : 0;
    }
    __syncthreads();
    if (!s_last) return;
    __threadfence();

    float nx = SENTC, ny = SENTC, nz = SENTC;
    if (slot < N) {
        float sx1f=0,sy1f=0,sx2f=0,sy2f=0,sx3f=0,sy3f=0, c3=0.f;
        int   z1=0,z2=0,z3=0, c1=0,c2=0;
        #pragma unroll 2
        for (int js2 = 0; js2 < JSPLIT; js2++) {
            const float4* p = (const float4*)(g_part + (js2 * NSLOTS_I + slot) * 12);
            float4 v0 = p[0], v1 = p[1], v2 = p[2];
            sx1f += v0.x; sy1f += v0.y; sx2f += v0.z; sy2f += v0.w;
            sx3f += v1.x; sy3f += v1.y;
            z1 += __float_as_int(v1.z); z2 += __float_as_int(v1.w);
            z3 += __float_as_int(v2.x);
            c1 += __float_as_int(v2.y); c2 += __float_as_int(v2.z); c3 += v2.w;
        }
        float sz1 = (float)z1 * (1.0f / ZSCALE);
        float sz2 = (float)z2 * (1.0f / ZSCALE);
        float sz3 = (float)z3 * (1.0f / ZSCALE);
        const float* wp = g_w + (it * N + slot) * 3;
        float e0 = wp[0], e1 = wp[1], e2 = wp[2];
        float inv = 1.0f / (e0 + e1 + e2);
        float r1 = e0 / (float)c1, r2 = e1 / (float)c2, r3 = e2 / c3;
        nx = (sx1f * r1 + sx2f * r2 + sx3f * r3) * inv;
        ny = (sy1f * r1 + sy2f * r2 + sy3f * r3) * inv;
        nz = (sz1 * r1 + sz2 * r2 + sz3 * r3) * inv;
        float* oo = out + (it * N + slot) * 3;
        oo[0] = nx; oo[1] = ny; oo[2] = nz;
    }
    if (it < ITERS - 1) write_rec(dstP, slot, nx, ny, nz);
}

// ---------------------------------------------------------------------------
// Inputs: 0:X 1:X_fea 2:W1 3:b1 4:gamma 5:beta 6:W2 7:b2   Output: [4,N,3] f32
// 7 launches; shift(it=0) at index 3 (ncu capture point).
// ---------------------------------------------------------------------------
extern "C" void kernel_launch(void* const* d_in, const int* in_sizes, int n_in,
                              void* d_out, int out_size) {
    const float* X     = (const float*)d_in[0];
    const float* Xfea  = (const float*)d_in[1];
    const float* W1    = (const float*)d_in[2];
    const float* b1    = (const float*)d_in[3];
    const float* gamma = (const float*)d_in[4];
    const float* beta  = (const float*)d_in[5];
    const float* W2    = (const float*)d_in[6];
    const float* b2    = (const float*)d_in[7];
    float* out = (float*)d_out;

    linear1_kernel<<<dim3((N + 127) / 128, ITERS), 128>>>(Xfea, W1, b1);        // 0
    bnstats_prep_kernel<<<ITERS, 1024>>>(X);                                     // 1
    logits_kernel<<<dim3((N + 255) / 256, ITERS), 256>>>(gamma, beta, W2, b2);   // 2
    for (int it = 0; it < ITERS; it++)                                           // 3..6
        shift_kernel<<<dim3(NITILE, JSPLIT), ITILE>>>(out, it);
}